// round 2
// baseline (speedup 1.0000x reference)
#include <cuda_runtime.h>
#include <math.h>

#define Bn 64
#define Dn 256
#define Hn 512
#define Rn 32
#define CLIPV 50.0f
#define TI 8
#define TB 8
#define NCH 4   // chunks of 128 floats covering Hn=512 per warp

// Output layout (concatenation of the returned tuple, fp32):
//   v_new      [64,512]      @ 0
//   new_h      [64,512]      @ 32768
//   dU_new     [64,512,512]  @ 65536
//   new_trace_e[64,512]      @ 16842752
//   new_trace_E[64,512,512]  @ 16875520
#define OFF_V    ((size_t)0)
#define OFF_NH   ((size_t)32768)
#define OFF_DU   ((size_t)65536)
#define OFF_TEO  ((size_t)16842752)
#define OFF_TEE  ((size_t)16875520)

__device__ float g_mod[Bn];

__device__ __forceinline__ float sigmoidf_(float x) {
    return 1.0f / (1.0f + expf(-x));
}

// ---------------------------------------------------------------------------
// mod[b] = sum_{r<32} relu( x[b]·x2h_w[512+r] + x2h_b[512+r]
//                         + h[b]·h2h_w[512+r] + h2h_b[512+r] )
// ---------------------------------------------------------------------------
__global__ void mod_kernel(const float* __restrict__ x,
                           const float* __restrict__ h,
                           const float* __restrict__ x2h_w,
                           const float* __restrict__ x2h_b,
                           const float* __restrict__ h2h_w,
                           const float* __restrict__ h2h_b) {
    const int b    = blockIdx.x;
    const int w    = threadIdx.x >> 5;
    const int lane = threadIdx.x & 31;
    __shared__ float sm[8];

    const float* xb = x + (size_t)b * Dn;
    const float* hb = h + (size_t)b * Hn;

    float acc = 0.f;
    for (int r = w; r < Rn; r += 8) {
        const int o = Hn + r;
        float s = 0.f;
        const float* xw = x2h_w + (size_t)o * Dn;
        for (int k = lane; k < Dn; k += 32) s = fmaf(xw[k], xb[k], s);
        const float* hw = h2h_w + (size_t)o * Hn;
        for (int k = lane; k < Hn; k += 32) s = fmaf(hw[k], hb[k], s);
#pragma unroll
        for (int off = 16; off; off >>= 1)
            s += __shfl_xor_sync(0xffffffffu, s, off);
        if (lane == 0) acc += fmaxf(s + x2h_b[o] + h2h_b[o], 0.f);
    }
    if (lane == 0) sm[w] = acc;
    __syncthreads();
    if (threadIdx.x == 0) {
        float m = 0.f;
#pragma unroll
        for (int ww = 0; ww < 8; ww++) m += sm[ww];
        g_mod[b] = m;
    }
}

// ---------------------------------------------------------------------------
// Fused main kernel — warp-per-row.
// Block = TI i-rows x TB batches, 128 threads = 4 warps.
// Each warp owns full (i,b) rows (2 i-rows x 8 batches = 16 rows).
// Lane covers j = c*128 + lane*4, c=0..3 (float4 chunks, 8 loads in flight).
// No per-row __syncthreads; single warp butterfly reduction per row.
// Clip bounds computed in-register per i (batch-independent).
// ---------------------------------------------------------------------------
__global__ __launch_bounds__(128) void sgru_main(
    const float* __restrict__ x, const float* __restrict__ h,
    const float* __restrict__ v, const float* __restrict__ dU,
    const float* __restrict__ trace_e, const float* __restrict__ trace_E,
    const float* __restrict__ x2h_w, const float* __restrict__ x2h_b,
    const float* __restrict__ h2h_w, const float* __restrict__ h2h_b,
    const float* __restrict__ alpha, const float* __restrict__ tau_v,
    const float* __restrict__ tau_e, const float* __restrict__ tau_U,
    const float* __restrict__ tau_E, float* __restrict__ out) {
    const int i0   = blockIdx.x * TI;
    const int b0   = blockIdx.y * TB;
    const int tid  = threadIdx.x;
    const int warp = tid >> 5;
    const int lane = tid & 31;

    __shared__ float sh_h[TB][Hn];
    __shared__ float sh_te[TB][Hn];
    __shared__ float sh_x[TB][Dn];

    for (int idx = tid; idx < TB * (Hn / 4); idx += 128) {
        const int bb = idx / (Hn / 4);
        const int jj = (idx % (Hn / 4)) * 4;
        *(float4*)&sh_h[bb][jj]  = *(const float4*)(h + (size_t)(b0 + bb) * Hn + jj);
        *(float4*)&sh_te[bb][jj] = *(const float4*)(trace_e + (size_t)(b0 + bb) * Hn + jj);
    }
    for (int idx = tid; idx < TB * (Dn / 4); idx += 128) {
        const int bb = idx / (Dn / 4);
        const int jj = (idx % (Dn / 4)) * 4;
        *(float4*)&sh_x[bb][jj] = *(const float4*)(x + (size_t)(b0 + bb) * Dn + jj);
    }
    __syncthreads();

    const float sU  = sigmoidf_(tau_U[0]);
    const float sE  = sigmoidf_(tau_E[0]);
    const float omU = 1.0f - sU;

    // Each warp processes i-rows ii = warp, warp+4 (TI=8, 4 warps).
    for (int ii = warp; ii < TI; ii += 4) {
        const int i = i0 + ii;
        const int jb = lane * 4;  // base column within a 128-float chunk

        // Per-i constants in registers, covering lane's 16 columns.
        float ar[NCH][4], Wr[NCH][4], up[NCH][4], lo[NCH][4];
#pragma unroll
        for (int c = 0; c < NCH; c++) {
            const int j = c * 128 + jb;
            const float4 A = *(const float4*)(alpha + (size_t)i * Hn + j);
            const float4 W = *(const float4*)(h2h_w + (size_t)i * Hn + j);
            ar[c][0] = fmaxf(A.x, 0.f); ar[c][1] = fmaxf(A.y, 0.f);
            ar[c][2] = fmaxf(A.z, 0.f); ar[c][3] = fmaxf(A.w, 0.f);
            Wr[c][0] = W.x; Wr[c][1] = W.y; Wr[c][2] = W.z; Wr[c][3] = W.w;
#pragma unroll
            for (int k = 0; k < 4; k++) {
                const float d = ar[c][k] + 1e-8f;
                up[c][k] =  fmaxf(CLIPV - Wr[c][k], 0.f) / d;
                lo[c][k] = -fmaxf(CLIPV + Wr[c][k], 0.f) / d;
            }
        }
        float xw[2][4];
#pragma unroll
        for (int c = 0; c < 2; c++) {
            const float4 X = *(const float4*)(x2h_w + (size_t)i * Dn + c * 128 + jb);
            xw[c][0] = X.x; xw[c][1] = X.y; xw[c][2] = X.z; xw[c][3] = X.w;
        }

        const float bias = x2h_b[i] + h2h_b[i];
        const float sv   = sigmoidf_(tau_v[i]);
        const float se   = sigmoidf_(tau_e[i]);

        for (int bb = 0; bb < TB; bb++) {
            const int b = b0 + bb;
            const size_t rowBase = ((size_t)b * Hn + i) * Hn;
            const float suMod = sU * g_mod[b];

            // 8 independent row loads (4 dU + 4 trace_E float4s)
            float4 du[NCH], tE[NCH];
#pragma unroll
            for (int c = 0; c < NCH; c++) {
                du[c] = *(const float4*)(dU + rowBase + c * 128 + jb);
                tE[c] = *(const float4*)(trace_E + rowBase + c * 128 + jb);
            }

            float hv[NCH][4], tev[NCH][4];
#pragma unroll
            for (int c = 0; c < NCH; c++) {
                const int j = c * 128 + jb;
                const float4 H4 = *(const float4*)&sh_h[bb][j];
                const float4 T4 = *(const float4*)&sh_te[bb][j];
                hv[c][0] = H4.x; hv[c][1] = H4.y; hv[c][2] = H4.z; hv[c][3] = H4.w;
                tev[c][0] = T4.x; tev[c][1] = T4.y; tev[c][2] = T4.z; tev[c][3] = T4.w;
            }

            // partial of dv = Wh + plastic (+ Wx over D=256)
            float p = 0.f;
#pragma unroll
            for (int c = 0; c < NCH; c++) {
                const float* dup = (const float*)&du[c];
#pragma unroll
                for (int k = 0; k < 4; k++) {
                    p = fmaf(ar[c][k] * dup[k] + Wr[c][k], hv[c][k], p);
                }
            }
#pragma unroll
            for (int c = 0; c < 2; c++) {
#pragma unroll
                for (int k = 0; k < 4; k++)
                    p = fmaf(xw[c][k], sh_x[bb][c * 128 + jb + k], p);
            }
#pragma unroll
            for (int off = 16; off; off >>= 1)
                p += __shfl_xor_sync(0xffffffffu, p, off);

            const float dv  = p + bias;
            const float vb  = v[(size_t)b * Hn + i];
            const float vn  = fmaf(sv, dv - vb, vb);
            const float nh  = fmaxf(vn, 0.f);
            const float nte = fmaf(se, sh_h[bb][i] - sh_te[bb][i], sh_te[bb][i]);
            if (lane == 0) {
                out[OFF_V   + (size_t)b * Hn + i] = vn;
                out[OFF_NH  + (size_t)b * Hn + i] = nh;
                out[OFF_TEO + (size_t)b * Hn + i] = nte;
            }

#pragma unroll
            for (int c = 0; c < NCH; c++) {
                const float* dup = (const float*)&du[c];
                const float* tEp = (const float*)&tE[c];
                float4 tOut, dOut;
                float* tO = (float*)&tOut;
                float* dO = (float*)&dOut;
#pragma unroll
                for (int k = 0; k < 4; k++) {
                    const float o  = nh * tev[c][k] - nte * hv[c][k];
                    const float t  = fmaf(sE, o - tEp[k], tEp[k]);
                    float d = fmaf(suMod, t, omU * dup[k]);
                    d = fmaxf(fminf(d, up[c][k]), lo[c][k]);
                    tO[k] = t;
                    dO[k] = d;
                }
                *(float4*)(out + OFF_TEE + rowBase + c * 128 + jb) = tOut;
                *(float4*)(out + OFF_DU  + rowBase + c * 128 + jb) = dOut;
            }
        }
    }
}

extern "C" void kernel_launch(void* const* d_in, const int* in_sizes, int n_in,
                              void* d_out, int out_size) {
    const float* x       = (const float*)d_in[0];
    const float* h       = (const float*)d_in[1];
    const float* v       = (const float*)d_in[2];
    const float* dU      = (const float*)d_in[3];
    const float* trace_e = (const float*)d_in[4];
    const float* trace_E = (const float*)d_in[5];
    const float* x2h_w   = (const float*)d_in[6];
    const float* x2h_b   = (const float*)d_in[7];
    const float* h2h_w   = (const float*)d_in[8];
    const float* h2h_b   = (const float*)d_in[9];
    const float* alpha   = (const float*)d_in[10];
    const float* tau_v   = (const float*)d_in[11];
    const float* tau_e   = (const float*)d_in[12];
    const float* tau_U   = (const float*)d_in[13];
    const float* tau_E   = (const float*)d_in[14];
    float* out = (float*)d_out;

    mod_kernel<<<Bn, 256>>>(x, h, x2h_w, x2h_b, h2h_w, h2h_b);
    dim3 grid(Hn / TI, Bn / TB);
    sgru_main<<<grid, 128>>>(x, h, v, dU, trace_e, trace_E, x2h_w, x2h_b,
                             h2h_w, h2h_b, alpha, tau_v, tau_e, tau_U, tau_E,
                             out);
}

// round 3
// speedup vs baseline: 1.1123x; 1.1123x over previous
#include <cuda_runtime.h>
#include <math.h>

#define Bn 64
#define Dn 256
#define Hn 512
#define Rn 32
#define CLIPV 50.0f
#define TB1 16   // batches per P1 block

// Output layout (concatenation of the returned tuple, fp32):
//   v_new      [64,512]      @ 0
//   new_h      [64,512]      @ 32768
//   dU_new     [64,512,512]  @ 65536
//   new_trace_e[64,512]      @ 16842752
//   new_trace_E[64,512,512]  @ 16875520
#define OFF_V    ((size_t)0)
#define OFF_NH   ((size_t)32768)
#define OFF_DU   ((size_t)65536)
#define OFF_TEO  ((size_t)16842752)
#define OFF_TEE  ((size_t)16875520)

// Device-global scratch (allocation-free)
__device__ float g_up[Hn * Hn];
__device__ float g_lo[Hn * Hn];
__device__ float g_suMod[Bn];
__device__ float g_sE;
__device__ float g_omU;

__device__ __forceinline__ float sigmoidf_(float x) {
    return 1.0f / (1.0f + expf(-x));
}

// ---------------------------------------------------------------------------
// Prep kernel. blocks [0,512): clip bounds row i = bx.
// blocks [512,576): mod[b]*sigmoid(tau_U) for b = bx-512; block 512 also
// writes the hoisted scalars sE and (1-sU). Hoisting sigmoids here keeps
// MUFU out of the 4M-thread streaming kernel.
// ---------------------------------------------------------------------------
__global__ __launch_bounds__(128) void prep_kernel(
    const float* __restrict__ h2h_w, const float* __restrict__ alpha,
    const float* __restrict__ x, const float* __restrict__ h,
    const float* __restrict__ x2h_w, const float* __restrict__ x2h_b,
    const float* __restrict__ h2h_b, const float* __restrict__ tau_U,
    const float* __restrict__ tau_E) {
    const int bx = blockIdx.x;
    if (bx < Hn) {
        const int i  = bx;
        const int j0 = threadIdx.x * 4;
        const float4 W = *(const float4*)(h2h_w + (size_t)i * Hn + j0);
        const float4 A = *(const float4*)(alpha + (size_t)i * Hn + j0);
        float4 up, lo;
        {
            const float d0 = fmaxf(A.x, 0.f) + 1e-8f;
            const float d1 = fmaxf(A.y, 0.f) + 1e-8f;
            const float d2 = fmaxf(A.z, 0.f) + 1e-8f;
            const float d3 = fmaxf(A.w, 0.f) + 1e-8f;
            up.x = fmaxf(CLIPV - W.x, 0.f) / d0;  lo.x = -fmaxf(CLIPV + W.x, 0.f) / d0;
            up.y = fmaxf(CLIPV - W.y, 0.f) / d1;  lo.y = -fmaxf(CLIPV + W.y, 0.f) / d1;
            up.z = fmaxf(CLIPV - W.z, 0.f) / d2;  lo.z = -fmaxf(CLIPV + W.z, 0.f) / d2;
            up.w = fmaxf(CLIPV - W.w, 0.f) / d3;  lo.w = -fmaxf(CLIPV + W.w, 0.f) / d3;
        }
        *(float4*)(g_up + (size_t)i * Hn + j0) = up;
        *(float4*)(g_lo + (size_t)i * Hn + j0) = lo;
        return;
    }
    // mod blocks
    const int b    = bx - Hn;
    const int w    = threadIdx.x >> 5;
    const int lane = threadIdx.x & 31;
    __shared__ float sm[4];

    const float* xb = x + (size_t)b * Dn;
    const float* hb = h + (size_t)b * Hn;

    float acc = 0.f;
    for (int r = w; r < Rn; r += 4) {
        const int o = Hn + r;
        float s = 0.f;
        const float* xw = x2h_w + (size_t)o * Dn;
        for (int k = lane; k < Dn; k += 32) s = fmaf(xw[k], xb[k], s);
        const float* hw = h2h_w + (size_t)o * Hn;
        for (int k = lane; k < Hn; k += 32) s = fmaf(hw[k], hb[k], s);
#pragma unroll
        for (int off = 16; off; off >>= 1)
            s += __shfl_xor_sync(0xffffffffu, s, off);
        if (lane == 0) acc += fmaxf(s + x2h_b[o] + h2h_b[o], 0.f);
    }
    if (lane == 0) sm[w] = acc;
    __syncthreads();
    if (threadIdx.x == 0) {
        const float mod = sm[0] + sm[1] + sm[2] + sm[3];
        const float sU  = sigmoidf_(tau_U[0]);
        g_suMod[b] = sU * mod;
        if (b == 0) {
            g_sE  = sigmoidf_(tau_E[0]);
            g_omU = 1.0f - sU;
        }
    }
}

// ---------------------------------------------------------------------------
// P1: reduction kernel. Warp-per-(i,b) row; each warp owns one i for TB1=16
// batches (alpha/W/x2h rows stay in registers across the b-loop).
// Computes dv = Wx + Wh + plastic, then v_new/new_h/new_trace_e.
// Reads dU once. No big epilogue -> low regs -> high occupancy.
// ---------------------------------------------------------------------------
__global__ __launch_bounds__(128) void p1_kernel(
    const float* __restrict__ x, const float* __restrict__ h,
    const float* __restrict__ v, const float* __restrict__ dU,
    const float* __restrict__ trace_e, const float* __restrict__ x2h_w,
    const float* __restrict__ x2h_b, const float* __restrict__ h2h_w,
    const float* __restrict__ h2h_b, const float* __restrict__ alpha,
    const float* __restrict__ tau_v, const float* __restrict__ tau_e,
    float* __restrict__ out) {
    const int warp = threadIdx.x >> 5;
    const int lane = threadIdx.x & 31;
    const int i    = blockIdx.x * 4 + warp;
    const int b0   = blockIdx.y * TB1;
    const int jb   = lane * 4;

    __shared__ float sh_h[TB1][Hn];
    __shared__ float sh_x[TB1][Dn];

    for (int idx = threadIdx.x; idx < TB1 * (Hn / 4); idx += 128) {
        const int bb = idx >> 7;          // Hn/4 = 128
        const int jj = (idx & 127) * 4;
        *(float4*)&sh_h[bb][jj] = *(const float4*)(h + (size_t)(b0 + bb) * Hn + jj);
    }
    for (int idx = threadIdx.x; idx < TB1 * (Dn / 4); idx += 128) {
        const int bb = idx >> 6;          // Dn/4 = 64
        const int jj = (idx & 63) * 4;
        *(float4*)&sh_x[bb][jj] = *(const float4*)(x + (size_t)(b0 + bb) * Dn + jj);
    }
    __syncthreads();

    // Per-i rows in registers (lane covers 4 chunks of 4 cols)
    float ar[4][4], Wr[4][4];
#pragma unroll
    for (int c = 0; c < 4; c++) {
        const int j = c * 128 + jb;
        const float4 A = *(const float4*)(alpha + (size_t)i * Hn + j);
        const float4 W = *(const float4*)(h2h_w + (size_t)i * Hn + j);
        ar[c][0] = fmaxf(A.x, 0.f); ar[c][1] = fmaxf(A.y, 0.f);
        ar[c][2] = fmaxf(A.z, 0.f); ar[c][3] = fmaxf(A.w, 0.f);
        Wr[c][0] = W.x; Wr[c][1] = W.y; Wr[c][2] = W.z; Wr[c][3] = W.w;
    }
    float xw[2][4];
#pragma unroll
    for (int c = 0; c < 2; c++) {
        const float4 X = *(const float4*)(x2h_w + (size_t)i * Dn + c * 128 + jb);
        xw[c][0] = X.x; xw[c][1] = X.y; xw[c][2] = X.z; xw[c][3] = X.w;
    }
    const float bias = x2h_b[i] + h2h_b[i];
    const float sv   = sigmoidf_(tau_v[i]);
    const float se   = sigmoidf_(tau_e[i]);

    for (int bb = 0; bb < TB1; bb++) {
        const int b = b0 + bb;
        const size_t rowBase = ((size_t)b * Hn + i) * Hn;

        float4 du[4];
#pragma unroll
        for (int c = 0; c < 4; c++)
            du[c] = *(const float4*)(dU + rowBase + c * 128 + jb);

        float p = 0.f;
#pragma unroll
        for (int c = 0; c < 4; c++) {
            const int j = c * 128 + jb;
            const float* dup = (const float*)&du[c];
            const float4 H4 = *(const float4*)&sh_h[bb][j];
            p = fmaf(fmaf(ar[c][0], dup[0], Wr[c][0]), H4.x, p);
            p = fmaf(fmaf(ar[c][1], dup[1], Wr[c][1]), H4.y, p);
            p = fmaf(fmaf(ar[c][2], dup[2], Wr[c][2]), H4.z, p);
            p = fmaf(fmaf(ar[c][3], dup[3], Wr[c][3]), H4.w, p);
        }
#pragma unroll
        for (int c = 0; c < 2; c++) {
            const float4 X4 = *(const float4*)&sh_x[bb][c * 128 + jb];
            p = fmaf(xw[c][0], X4.x, p);
            p = fmaf(xw[c][1], X4.y, p);
            p = fmaf(xw[c][2], X4.z, p);
            p = fmaf(xw[c][3], X4.w, p);
        }
#pragma unroll
        for (int off = 16; off; off >>= 1)
            p += __shfl_xor_sync(0xffffffffu, p, off);

        if (lane == 0) {
            const float dv  = p + bias;
            const float vb  = v[(size_t)b * Hn + i];
            const float vn  = fmaf(sv, dv - vb, vb);
            const float nh  = fmaxf(vn, 0.f);
            const float teo = trace_e[(size_t)b * Hn + i];
            const float nte = fmaf(se, sh_h[bb][i] - teo, teo);
            out[OFF_V   + (size_t)b * Hn + i] = vn;
            out[OFF_NH  + (size_t)b * Hn + i] = nh;
            out[OFF_TEO + (size_t)b * Hn + i] = nte;
        }
    }
}

// ---------------------------------------------------------------------------
// P2: pure streaming elementwise pass over the HxH matrices.
// Task = one float4 at linear index t = ((b*512)+i)*128 + j4.
// 2 independent tasks per thread for MLP. Streaming stores (__stcs) keep
// the write-once outputs from evicting the L2-hot dU / up / lo / h / te.
// ---------------------------------------------------------------------------
#define P2_BLOCKS 8192
#define P2_THREADS 256
#define P2_TOTAL  ((size_t)Bn * Hn * 128)           // 4,194,304 float4 tasks
#define P2_HALF   (P2_TOTAL / 2)

__global__ __launch_bounds__(P2_THREADS) void p2_kernel(
    const float* __restrict__ dU, const float* __restrict__ trace_E,
    const float* __restrict__ h, const float* __restrict__ trace_e,
    float* __restrict__ out) {
    const size_t gid = (size_t)blockIdx.x * P2_THREADS + threadIdx.x;
    const float sE  = g_sE;
    const float omU = g_omU;

    const float4* dU4 = (const float4*)dU;
    const float4* tE4 = (const float4*)trace_E;
    const float4* h4p = (const float4*)h;
    const float4* te4p = (const float4*)trace_e;
    const float4* up4 = (const float4*)g_up;
    const float4* lo4 = (const float4*)g_lo;
    float4* outDU = (float4*)(out + OFF_DU);
    float4* outTE = (float4*)(out + OFF_TEE);

#pragma unroll
    for (int half = 0; half < 2; half++) {
        const size_t t = gid + (size_t)half * P2_HALF;
        const int j4  = (int)(t & 127);
        const size_t row = t >> 7;           // b*512 + i
        const int i = (int)(row & 511);
        const int b = (int)(row >> 9);

        const float4 du = dU4[t];
        const float4 tE = tE4[t];
        const float4 hh = h4p[((size_t)b << 7) + j4];
        const float4 te = te4p[((size_t)b << 7) + j4];
        const float4 up = up4[((size_t)i << 7) + j4];
        const float4 lo = lo4[((size_t)i << 7) + j4];
        const float nh  = out[OFF_NH  + row];
        const float nte = out[OFF_TEO + row];
        const float suMod = g_suMod[b];

        float4 tOut, dOut;
        {
            const float o = nh * te.x - nte * hh.x;
            tOut.x = fmaf(sE, o - tE.x, tE.x);
            dOut.x = fmaxf(fminf(fmaf(suMod, tOut.x, omU * du.x), up.x), lo.x);
        }
        {
            const float o = nh * te.y - nte * hh.y;
            tOut.y = fmaf(sE, o - tE.y, tE.y);
            dOut.y = fmaxf(fminf(fmaf(suMod, tOut.y, omU * du.y), up.y), lo.y);
        }
        {
            const float o = nh * te.z - nte * hh.z;
            tOut.z = fmaf(sE, o - tE.z, tE.z);
            dOut.z = fmaxf(fminf(fmaf(suMod, tOut.z, omU * du.z), up.z), lo.z);
        }
        {
            const float o = nh * te.w - nte * hh.w;
            tOut.w = fmaf(sE, o - tE.w, tE.w);
            dOut.w = fmaxf(fminf(fmaf(suMod, tOut.w, omU * du.w), up.w), lo.w);
        }
        __stcs(&outTE[t], tOut);
        __stcs(&outDU[t], dOut);
    }
}

extern "C" void kernel_launch(void* const* d_in, const int* in_sizes, int n_in,
                              void* d_out, int out_size) {
    const float* x       = (const float*)d_in[0];
    const float* h       = (const float*)d_in[1];
    const float* v       = (const float*)d_in[2];
    const float* dU      = (const float*)d_in[3];
    const float* trace_e = (const float*)d_in[4];
    const float* trace_E = (const float*)d_in[5];
    const float* x2h_w   = (const float*)d_in[6];
    const float* x2h_b   = (const float*)d_in[7];
    const float* h2h_w   = (const float*)d_in[8];
    const float* h2h_b   = (const float*)d_in[9];
    const float* alpha   = (const float*)d_in[10];
    const float* tau_v   = (const float*)d_in[11];
    const float* tau_e   = (const float*)d_in[12];
    const float* tau_U   = (const float*)d_in[13];
    const float* tau_E   = (const float*)d_in[14];
    float* out = (float*)d_out;

    prep_kernel<<<Hn + Bn, 128>>>(h2h_w, alpha, x, h, x2h_w, x2h_b, h2h_b,
                                  tau_U, tau_E);
    dim3 g1(Hn / 4, Bn / TB1);
    p1_kernel<<<g1, 128>>>(x, h, v, dU, trace_e, x2h_w, x2h_b, h2h_w, h2h_b,
                           alpha, tau_v, tau_e, out);
    p2_kernel<<<P2_BLOCKS, P2_THREADS>>>(dU, trace_E, h, trace_e, out);
}

// round 4
// speedup vs baseline: 1.3704x; 1.2320x over previous
#include <cuda_runtime.h>
#include <math.h>

#define Bn 64
#define Dn 256
#define Hn 512
#define Rn 32
#define CLIPV 50.0f
#define TB1 16   // batches per P1 block

// Output layout (concatenation of the returned tuple, fp32):
//   v_new      [64,512]      @ 0
//   new_h      [64,512]      @ 32768
//   dU_new     [64,512,512]  @ 65536
//   new_trace_e[64,512]      @ 16842752
//   new_trace_E[64,512,512]  @ 16875520
#define OFF_V    ((size_t)0)
#define OFF_NH   ((size_t)32768)
#define OFF_DU   ((size_t)65536)
#define OFF_TEO  ((size_t)16842752)
#define OFF_TEE  ((size_t)16875520)

// Device-global scratch (allocation-free)
__device__ float g_up[Hn * Hn];
__device__ float g_lo[Hn * Hn];
__device__ float g_suMod[Bn];
__device__ float g_sE;
__device__ float g_omU;

__device__ __forceinline__ float sigmoidf_(float x) {
    return 1.0f / (1.0f + expf(-x));
}

// ---------------------------------------------------------------------------
// mod kernel: 64 blocks x 256 threads. Warp w handles rows r = w + 8*t
// (t<4) of the R=32 gate rows; float4 lane loads give 6 independent loads
// per row (vs 24 strided scalars before) -> latency-bound time ~4x lower.
// Writes g_suMod[b] = sigmoid(tau_U) * mod[b], plus hoisted scalars.
// ---------------------------------------------------------------------------
__global__ __launch_bounds__(256) void mod_kernel(
    const float* __restrict__ x, const float* __restrict__ h,
    const float* __restrict__ x2h_w, const float* __restrict__ x2h_b,
    const float* __restrict__ h2h_w, const float* __restrict__ h2h_b,
    const float* __restrict__ tau_U, const float* __restrict__ tau_E) {
    const int b    = blockIdx.x;
    const int w    = threadIdx.x >> 5;
    const int lane = threadIdx.x & 31;
    const int jb   = lane * 4;
    __shared__ float sm[8];

    const float4* xb = (const float4*)(x + (size_t)b * Dn);
    const float4* hb = (const float4*)(h + (size_t)b * Hn);

    float acc = 0.f;
#pragma unroll
    for (int t = 0; t < 4; t++) {
        const int r = w + 8 * t;
        const int o = Hn + r;
        const float4* xw = (const float4*)(x2h_w + (size_t)o * Dn);
        const float4* hw = (const float4*)(h2h_w + (size_t)o * Hn);

        // 6 independent float4 loads (2 over D=256, 4 over H=512)
        float s = 0.f;
#pragma unroll
        for (int c = 0; c < 2; c++) {
            const float4 W4 = xw[c * 32 + lane];
            const float4 V4 = xb[c * 32 + lane];
            s = fmaf(W4.x, V4.x, s); s = fmaf(W4.y, V4.y, s);
            s = fmaf(W4.z, V4.z, s); s = fmaf(W4.w, V4.w, s);
        }
#pragma unroll
        for (int c = 0; c < 4; c++) {
            const float4 W4 = hw[c * 32 + lane];
            const float4 V4 = hb[c * 32 + lane];
            s = fmaf(W4.x, V4.x, s); s = fmaf(W4.y, V4.y, s);
            s = fmaf(W4.z, V4.z, s); s = fmaf(W4.w, V4.w, s);
        }
#pragma unroll
        for (int off = 16; off; off >>= 1)
            s += __shfl_xor_sync(0xffffffffu, s, off);
        if (lane == 0) acc += fmaxf(s + x2h_b[o] + h2h_b[o], 0.f);
    }
    if (lane == 0) sm[w] = acc;
    __syncthreads();
    if (threadIdx.x == 0) {
        float m = 0.f;
#pragma unroll
        for (int ww = 0; ww < 8; ww++) m += sm[ww];
        const float sU = sigmoidf_(tau_U[0]);
        g_suMod[b] = sU * m;
        if (b == 0) {
            g_sE  = sigmoidf_(tau_E[0]);
            g_omU = 1.0f - sU;
        }
    }
}

// ---------------------------------------------------------------------------
// P1: reduction kernel, warp-per-(i,b) row, 2 rows in flight per iteration
// (8 independent float4 loads, two interleaved butterfly chains).
// blockIdx.y==0 blocks additionally compute+store the clip bounds for their
// i-rows (inputs alpha/W already in registers) -> prep kernel eliminated.
// ---------------------------------------------------------------------------
__global__ __launch_bounds__(128) void p1_kernel(
    const float* __restrict__ x, const float* __restrict__ h,
    const float* __restrict__ v, const float* __restrict__ dU,
    const float* __restrict__ trace_e, const float* __restrict__ x2h_w,
    const float* __restrict__ x2h_b, const float* __restrict__ h2h_w,
    const float* __restrict__ h2h_b, const float* __restrict__ alpha,
    const float* __restrict__ tau_v, const float* __restrict__ tau_e,
    float* __restrict__ out) {
    const int warp = threadIdx.x >> 5;
    const int lane = threadIdx.x & 31;
    const int i    = blockIdx.x * 4 + warp;
    const int b0   = blockIdx.y * TB1;
    const int jb   = lane * 4;

    __shared__ float sh_h[TB1][Hn];
    __shared__ float sh_x[TB1][Dn];

    for (int idx = threadIdx.x; idx < TB1 * (Hn / 4); idx += 128) {
        const int bb = idx >> 7;
        const int jj = (idx & 127) * 4;
        *(float4*)&sh_h[bb][jj] = *(const float4*)(h + (size_t)(b0 + bb) * Hn + jj);
    }
    for (int idx = threadIdx.x; idx < TB1 * (Dn / 4); idx += 128) {
        const int bb = idx >> 6;
        const int jj = (idx & 63) * 4;
        *(float4*)&sh_x[bb][jj] = *(const float4*)(x + (size_t)(b0 + bb) * Dn + jj);
    }
    __syncthreads();

    // Per-i rows in registers (lane covers 4 chunks of 4 cols)
    float ar[4][4], Wr[4][4];
#pragma unroll
    for (int c = 0; c < 4; c++) {
        const int j = c * 128 + jb;
        const float4 A = *(const float4*)(alpha + (size_t)i * Hn + j);
        const float4 W = *(const float4*)(h2h_w + (size_t)i * Hn + j);
        ar[c][0] = fmaxf(A.x, 0.f); ar[c][1] = fmaxf(A.y, 0.f);
        ar[c][2] = fmaxf(A.z, 0.f); ar[c][3] = fmaxf(A.w, 0.f);
        Wr[c][0] = W.x; Wr[c][1] = W.y; Wr[c][2] = W.z; Wr[c][3] = W.w;
    }

    // Fold the old prep kernel: one block column computes clip bounds.
    if (blockIdx.y == 0) {
#pragma unroll
        for (int c = 0; c < 4; c++) {
            const int j = c * 128 + jb;
            float4 up, lo;
            float* u = (float*)&up;
            float* l = (float*)&lo;
#pragma unroll
            for (int k = 0; k < 4; k++) {
                const float d = ar[c][k] + 1e-8f;
                u[k] =  fmaxf(CLIPV - Wr[c][k], 0.f) / d;
                l[k] = -fmaxf(CLIPV + Wr[c][k], 0.f) / d;
            }
            *(float4*)(g_up + (size_t)i * Hn + j) = up;
            *(float4*)(g_lo + (size_t)i * Hn + j) = lo;
        }
    }

    float xw[2][4];
#pragma unroll
    for (int c = 0; c < 2; c++) {
        const float4 X = *(const float4*)(x2h_w + (size_t)i * Dn + c * 128 + jb);
        xw[c][0] = X.x; xw[c][1] = X.y; xw[c][2] = X.z; xw[c][3] = X.w;
    }
    const float bias = x2h_b[i] + h2h_b[i];
    const float sv   = sigmoidf_(tau_v[i]);
    const float se   = sigmoidf_(tau_e[i]);

    for (int bb = 0; bb < TB1; bb += 2) {
        const int bA = b0 + bb;
        const int bB = b0 + bb + 1;
        const size_t rowA = ((size_t)bA * Hn + i) * Hn;
        const size_t rowB = ((size_t)bB * Hn + i) * Hn;

        // 8 independent row loads
        float4 duA[4], duB[4];
#pragma unroll
        for (int c = 0; c < 4; c++) {
            duA[c] = *(const float4*)(dU + rowA + c * 128 + jb);
            duB[c] = *(const float4*)(dU + rowB + c * 128 + jb);
        }

        float p = 0.f, q = 0.f;
#pragma unroll
        for (int c = 0; c < 4; c++) {
            const int j = c * 128 + jb;
            const float* dA = (const float*)&duA[c];
            const float* dB = (const float*)&duB[c];
            const float4 HA = *(const float4*)&sh_h[bb][j];
            const float4 HB = *(const float4*)&sh_h[bb + 1][j];
            p = fmaf(fmaf(ar[c][0], dA[0], Wr[c][0]), HA.x, p);
            q = fmaf(fmaf(ar[c][0], dB[0], Wr[c][0]), HB.x, q);
            p = fmaf(fmaf(ar[c][1], dA[1], Wr[c][1]), HA.y, p);
            q = fmaf(fmaf(ar[c][1], dB[1], Wr[c][1]), HB.y, q);
            p = fmaf(fmaf(ar[c][2], dA[2], Wr[c][2]), HA.z, p);
            q = fmaf(fmaf(ar[c][2], dB[2], Wr[c][2]), HB.z, q);
            p = fmaf(fmaf(ar[c][3], dA[3], Wr[c][3]), HA.w, p);
            q = fmaf(fmaf(ar[c][3], dB[3], Wr[c][3]), HB.w, q);
        }
#pragma unroll
        for (int c = 0; c < 2; c++) {
            const float4 XA = *(const float4*)&sh_x[bb][c * 128 + jb];
            const float4 XB = *(const float4*)&sh_x[bb + 1][c * 128 + jb];
            p = fmaf(xw[c][0], XA.x, p);  q = fmaf(xw[c][0], XB.x, q);
            p = fmaf(xw[c][1], XA.y, p);  q = fmaf(xw[c][1], XB.y, q);
            p = fmaf(xw[c][2], XA.z, p);  q = fmaf(xw[c][2], XB.z, q);
            p = fmaf(xw[c][3], XA.w, p);  q = fmaf(xw[c][3], XB.w, q);
        }
        // interleaved butterflies: two independent chains overlap
#pragma unroll
        for (int off = 16; off; off >>= 1) {
            p += __shfl_xor_sync(0xffffffffu, p, off);
            q += __shfl_xor_sync(0xffffffffu, q, off);
        }

        if (lane == 0) {
            {
                const float dv  = p + bias;
                const float vb  = v[(size_t)bA * Hn + i];
                const float vn  = fmaf(sv, dv - vb, vb);
                const float teo = trace_e[(size_t)bA * Hn + i];
                out[OFF_V   + (size_t)bA * Hn + i] = vn;
                out[OFF_NH  + (size_t)bA * Hn + i] = fmaxf(vn, 0.f);
                out[OFF_TEO + (size_t)bA * Hn + i] = fmaf(se, sh_h[bb][i] - teo, teo);
            }
            {
                const float dv  = q + bias;
                const float vb  = v[(size_t)bB * Hn + i];
                const float vn  = fmaf(sv, dv - vb, vb);
                const float teo = trace_e[(size_t)bB * Hn + i];
                out[OFF_V   + (size_t)bB * Hn + i] = vn;
                out[OFF_NH  + (size_t)bB * Hn + i] = fmaxf(vn, 0.f);
                out[OFF_TEO + (size_t)bB * Hn + i] = fmaf(se, sh_h[bb + 1][i] - teo, teo);
            }
        }
    }
}

// ---------------------------------------------------------------------------
// P2: pure streaming elementwise pass over the HxH matrices.
// trace_E via __ldcs (zero reuse) so it doesn't evict the L2-warm dU.
// ---------------------------------------------------------------------------
#define P2_BLOCKS 8192
#define P2_THREADS 256
#define P2_TOTAL  ((size_t)Bn * Hn * 128)
#define P2_HALF   (P2_TOTAL / 2)

__global__ __launch_bounds__(P2_THREADS) void p2_kernel(
    const float* __restrict__ dU, const float* __restrict__ trace_E,
    const float* __restrict__ h, const float* __restrict__ trace_e,
    float* __restrict__ out) {
    const size_t gid = (size_t)blockIdx.x * P2_THREADS + threadIdx.x;
    const float sE  = g_sE;
    const float omU = g_omU;

    const float4* dU4 = (const float4*)dU;
    const float4* tE4 = (const float4*)trace_E;
    const float4* h4p = (const float4*)h;
    const float4* te4p = (const float4*)trace_e;
    const float4* up4 = (const float4*)g_up;
    const float4* lo4 = (const float4*)g_lo;
    float4* outDU = (float4*)(out + OFF_DU);
    float4* outTE = (float4*)(out + OFF_TEE);

#pragma unroll
    for (int half = 0; half < 2; half++) {
        const size_t t = gid + (size_t)half * P2_HALF;
        const int j4  = (int)(t & 127);
        const size_t row = t >> 7;           // b*512 + i
        const int i = (int)(row & 511);
        const int b = (int)(row >> 9);

        const float4 du = dU4[t];
        const float4 tE = __ldcs(&tE4[t]);
        const float4 hh = h4p[((size_t)b << 7) + j4];
        const float4 te = te4p[((size_t)b << 7) + j4];
        const float4 up = up4[((size_t)i << 7) + j4];
        const float4 lo = lo4[((size_t)i << 7) + j4];
        const float nh  = __ldg(out + OFF_NH  + row);
        const float nte = __ldg(out + OFF_TEO + row);
        const float suMod = g_suMod[b];

        float4 tOut, dOut;
        {
            const float o = nh * te.x - nte * hh.x;
            tOut.x = fmaf(sE, o - tE.x, tE.x);
            dOut.x = fmaxf(fminf(fmaf(suMod, tOut.x, omU * du.x), up.x), lo.x);
        }
        {
            const float o = nh * te.y - nte * hh.y;
            tOut.y = fmaf(sE, o - tE.y, tE.y);
            dOut.y = fmaxf(fminf(fmaf(suMod, tOut.y, omU * du.y), up.y), lo.y);
        }
        {
            const float o = nh * te.z - nte * hh.z;
            tOut.z = fmaf(sE, o - tE.z, tE.z);
            dOut.z = fmaxf(fminf(fmaf(suMod, tOut.z, omU * du.z), up.z), lo.z);
        }
        {
            const float o = nh * te.w - nte * hh.w;
            tOut.w = fmaf(sE, o - tE.w, tE.w);
            dOut.w = fmaxf(fminf(fmaf(suMod, tOut.w, omU * du.w), up.w), lo.w);
        }
        __stcs(&outTE[t], tOut);
        __stcs(&outDU[t], dOut);
    }
}

extern "C" void kernel_launch(void* const* d_in, const int* in_sizes, int n_in,
                              void* d_out, int out_size) {
    const float* x       = (const float*)d_in[0];
    const float* h       = (const float*)d_in[1];
    const float* v       = (const float*)d_in[2];
    const float* dU      = (const float*)d_in[3];
    const float* trace_e = (const float*)d_in[4];
    const float* trace_E = (const float*)d_in[5];
    const float* x2h_w   = (const float*)d_in[6];
    const float* x2h_b   = (const float*)d_in[7];
    const float* h2h_w   = (const float*)d_in[8];
    const float* h2h_b   = (const float*)d_in[9];
    const float* alpha   = (const float*)d_in[10];
    const float* tau_v   = (const float*)d_in[11];
    const float* tau_e   = (const float*)d_in[12];
    const float* tau_U   = (const float*)d_in[13];
    const float* tau_E   = (const float*)d_in[14];
    float* out = (float*)d_out;

    mod_kernel<<<Bn, 256>>>(x, h, x2h_w, x2h_b, h2h_w, h2h_b, tau_U, tau_E);
    dim3 g1(Hn / 4, Bn / TB1);
    p1_kernel<<<g1, 128>>>(x, h, v, dU, trace_e, x2h_w, x2h_b, h2h_w, h2h_b,
                           alpha, tau_v, tau_e, out);
    p2_kernel<<<P2_BLOCKS, P2_THREADS>>>(dU, trace_E, h, trace_e, out);
}